// round 4
// baseline (speedup 1.0000x reference)
#include <cuda_runtime.h>
#include <cstdint>

#define BB    8
#define NN    4096
#define KNB   20
#define NPTS  (BB * NN)          /* 32768  */
#define M1    (NPTS * KNB)       /* 655360 */
#define EPSB  1e-5f
#define PMAX  8192

/* ================= static device scratch (no allocations) ============= */
__device__ int   g_idx[M1];                               /* knn indices        */
__device__ float g_hbuf1[(size_t)M1 * 64];                /* y1 then h1 [M1,64] */
__device__ float g_ybuf2[(size_t)M1 * 128];               /* y2 [M1,128]        */
__device__ float g_cat[(size_t)NPTS * 192];               /* [x1|x2] [P,192]    */
__device__ float g_ybuf3[(size_t)NPTS * 256];             /* y3 [P,256]         */
__device__ float g_w2t[64 * 128];                         /* W2^T [k][o]        */
__device__ float g_w3t[192 * 256];                        /* W3^T [k][o]        */
__device__ float g_psum[(size_t)448 * PMAX];              /* per-block partials */
__device__ float g_psq [(size_t)448 * PMAX];
__device__ float g_mu[448];
__device__ float g_rs[448];

/* ================= f32x2 packed-math helpers ========================= */
__device__ __forceinline__ double pack2(float x, float y) {
    double d;
    asm("mov.b64 %0, {%1, %2};" : "=d"(d) : "f"(x), "f"(y));
    return d;
}
__device__ __forceinline__ float2 unpack2(double d) {
    float2 r;
    asm("mov.b64 {%0, %1}, %2;" : "=f"(r.x), "=f"(r.y) : "d"(d));
    return r;
}
__device__ __forceinline__ double ffma2(double a, double b, double c) {
    double d;
    asm("fma.rn.f32x2 %0, %1, %2, %3;" : "=d"(d) : "d"(a), "d"(b), "d"(c));
    return d;
}

/* ================= prep: transpose W2, W3 ============================ */
__global__ void prep_kernel(const float* __restrict__ W2,
                            const float* __restrict__ W3) {
    int t = blockIdx.x * blockDim.x + threadIdx.x;
    if (t < 64 * 128) {
        int k = t / 128, o = t % 128;
        g_w2t[t] = W2[o * 64 + k];
    }
    if (t < 192 * 256) {
        int k = t / 256, o = t % 256;
        g_w3t[t] = W3[o * 192 + k];
    }
}

/* ================= kNN =============================================== */
/* key v = 2 q.m - |m|^2 = (-|q-m|^2) + |q|^2 : same ordering as dist.   */
#define KCHUNK 2048
__global__ void knn_kernel(const float* __restrict__ x) {
    __shared__ float4 pts[KCHUNK];
    const int b = blockIdx.x;
    const int n = blockIdx.y * blockDim.x + threadIdx.x;
    const float* xb = x + b * 3 * NN;
    const float qx = xb[n], qy = xb[NN + n], qz = xb[2 * NN + n];
    const float q2x = 2.f * qx, q2y = 2.f * qy, q2z = 2.f * qz;

    float bv[KNB];
    int   bi[KNB];
    float vmin;
    int   mp;

    /* chunk 0 load */
    for (int m = threadIdx.x; m < KCHUNK; m += blockDim.x) {
        float px = xb[m], py = xb[NN + m], pz = xb[2 * NN + m];
        pts[m] = make_float4(px, py, pz, fmaf(px, px, fmaf(py, py, pz * pz)));
    }
    __syncthreads();

#pragma unroll
    for (int m = 0; m < KNB; ++m) {
        float4 p = pts[m];
        bv[m] = fmaf(q2x, p.x, fmaf(q2y, p.y, fmaf(q2z, p.z, -p.w)));
        bi[m] = m;
    }
    vmin = bv[0]; mp = 0;
#pragma unroll
    for (int t = 1; t < KNB; ++t) if (bv[t] < vmin) { vmin = bv[t]; mp = t; }

    for (int m = KNB; m < KCHUNK; ++m) {
        float4 p = pts[m];
        float v = fmaf(q2x, p.x, fmaf(q2y, p.y, fmaf(q2z, p.z, -p.w)));
        if (v > vmin) {
            bv[mp] = v; bi[mp] = m;
            vmin = bv[0]; mp = 0;
#pragma unroll
            for (int t = 1; t < KNB; ++t) if (bv[t] < vmin) { vmin = bv[t]; mp = t; }
        }
    }
    for (int base = KCHUNK; base < NN; base += KCHUNK) {
        __syncthreads();
        for (int m = threadIdx.x; m < KCHUNK; m += blockDim.x) {
            float px = xb[base + m], py = xb[NN + base + m], pz = xb[2 * NN + base + m];
            pts[m] = make_float4(px, py, pz, fmaf(px, px, fmaf(py, py, pz * pz)));
        }
        __syncthreads();
        for (int m = 0; m < KCHUNK; ++m) {
            float4 p = pts[m];
            float v = fmaf(q2x, p.x, fmaf(q2y, p.y, fmaf(q2z, p.z, -p.w)));
            if (v > vmin) {
                bv[mp] = v; bi[mp] = base + m;
                vmin = bv[0]; mp = 0;
#pragma unroll
                for (int t = 1; t < KNB; ++t) if (bv[t] < vmin) { vmin = bv[t]; mp = t; }
            }
        }
    }
    int* op = g_idx + (size_t)(b * NN + n) * KNB;
#pragma unroll
    for (int t = 0; t < KNB; ++t) op[t] = bi[t];
}

/* ================= y1 = W1 @ feat, + BN1 partials ==================== */
/* block 256 = (o:64, lane:4); grid 2560 blocks; 256 rows per block.     */
__global__ void y1_kernel(const float* __restrict__ x,
                          const float* __restrict__ W1) {
    const int o    = threadIdx.x & 63;
    const int lane = threadIdx.x >> 6;
    float wr[6];
#pragma unroll
    for (int c = 0; c < 6; ++c) wr[c] = W1[o * 6 + c];

    float lsum = 0.f, lsq = 0.f;
    const int rbase = blockIdx.x * 256;
    for (int r = lane; r < 256; r += 4) {
        const int m  = rbase + r;
        const int p  = m / KNB;
        const int b  = p >> 12;
        const int n  = p & (NN - 1);
        const float* xb = x + b * 3 * NN;
        const int nb = g_idx[m];
        const float cx = xb[n], cy = xb[NN + n], cz = xb[2 * NN + n];
        const float f0 = xb[nb] - cx;
        const float f1 = xb[NN + nb] - cy;
        const float f2 = xb[2 * NN + nb] - cz;
        float y = wr[0] * f0;
        y = fmaf(wr[1], f1, y);
        y = fmaf(wr[2], f2, y);
        y = fmaf(wr[3], cx, y);
        y = fmaf(wr[4], cy, y);
        y = fmaf(wr[5], cz, y);
        g_hbuf1[(size_t)m * 64 + o] = y;
        lsum += y;
        lsq  = fmaf(y, y, lsq);
    }
    __shared__ float rsum[4][64], rsq[4][64];
    rsum[lane][o] = lsum;
    rsq[lane][o]  = lsq;
    __syncthreads();
    if (lane == 0) {
        float s = rsum[0][o] + rsum[1][o] + rsum[2][o] + rsum[3][o];
        float q = rsq[0][o] + rsq[1][o] + rsq[2][o] + rsq[3][o];
        g_psum[(size_t)o * PMAX + blockIdx.x] = s;
        g_psq [(size_t)o * PMAX + blockIdx.x] = q;
    }
}

/* ================= finalize BN stats ================================= */
__global__ void finalize_kernel(int off, int P, float invM) {
    const int c = off + blockIdx.x;
    __shared__ float ss[256], qq[256];
    float s = 0.f, q = 0.f;
    for (int i = threadIdx.x; i < P; i += 256) {
        s += g_psum[(size_t)c * PMAX + i];
        q += g_psq [(size_t)c * PMAX + i];
    }
    ss[threadIdx.x] = s;
    qq[threadIdx.x] = q;
    __syncthreads();
    for (int w = 128; w > 0; w >>= 1) {
        if (threadIdx.x < w) {
            ss[threadIdx.x] += ss[threadIdx.x + w];
            qq[threadIdx.x] += qq[threadIdx.x + w];
        }
        __syncthreads();
    }
    if (threadIdx.x == 0) {
        float mu  = ss[0] * invM;
        float var = qq[0] * invM - mu * mu;
        g_mu[c] = mu;
        g_rs[c] = rsqrtf(var + EPSB);
    }
}

/* ================= h1 = BN+ReLU (in place) + attn-pool x1 ============ */
/* block 256 = (o:64, pt:4); grid NPTS/4.                                */
__global__ void h1pool_kernel(const float* __restrict__ g1,
                              const float* __restrict__ b1) {
    const int o  = threadIdx.x & 63;
    const int pl = threadIdx.x >> 6;
    const int p  = blockIdx.x * 4 + pl;
    const float mu = g_mu[o], rs = g_rs[o], gg = g1[o], bb = b1[o];
    float h[KNB];
    float hmax = -1e30f;
    float* base = g_hbuf1 + (size_t)p * KNB * 64 + o;
#pragma unroll
    for (int kk = 0; kk < KNB; ++kk) {
        float y  = base[(size_t)kk * 64];
        float hv = fmaxf(fmaf((y - mu) * rs, gg, bb), 0.f);
        h[kk] = hv;
        base[(size_t)kk * 64] = hv;
        hmax = fmaxf(hmax, hv);
    }
    float se = 0.f, sw = 0.f;
#pragma unroll
    for (int kk = 0; kk < KNB; ++kk) {
        float e = __expf(h[kk] - hmax);
        se += e;
        sw = fmaf(e, h[kk], sw);
    }
    g_cat[(size_t)p * 192 + o] = sw / se;
}

/* ================= h2 = BN+ReLU + attn-pool x2 ======================= */
/* block 128 = o; grid NPTS.                                             */
__global__ void h2pool_kernel(const float* __restrict__ g2,
                              const float* __restrict__ b2) {
    const int o = threadIdx.x;
    const int p = blockIdx.x;
    const float mu = g_mu[64 + o], rs = g_rs[64 + o], gg = g2[o], bb = b2[o];
    float h[KNB];
    float hmax = -1e30f;
    const float* base = g_ybuf2 + (size_t)p * KNB * 128 + o;
#pragma unroll
    for (int kk = 0; kk < KNB; ++kk) {
        float y  = base[(size_t)kk * 128];
        float hv = fmaxf(fmaf((y - mu) * rs, gg, bb), 0.f);
        h[kk] = hv;
        hmax = fmaxf(hmax, hv);
    }
    float se = 0.f, sw = 0.f;
#pragma unroll
    for (int kk = 0; kk < KNB; ++kk) {
        float e = __expf(h[kk] - hmax);
        se += e;
        sw = fmaf(e, h[kk], sw);
    }
    g_cat[(size_t)p * 192 + 64 + o] = sw / se;
}

/* ================= tiled GEMM (f32x2) + BN partials ================== */
/* C[M,NCOLS] = A[M,KTOT] * Bt[KTOT,NCOLS].  128x128x32 tiles,           */
/* 256 thr (16x16), 8x8 micro-tile, packed fma.rn.f32x2.                 */
#define BMg 128
#define BNg 128
#define BKg 32

template <int KTOT, int NCOLS>
__global__ void gemm_kernel(const float* __restrict__ A,
                            const float* __restrict__ Bt,
                            float* __restrict__ C,
                            int statoff) {
    __shared__ float As[BKg][BMg + 4];    /* [k][m], padded            */
    __shared__ float Bs[BKg][BNg];        /* [k][n]                    */
    __shared__ float red[16][BNg];

    const int tx = threadIdx.x & 15;
    const int ty = threadIdx.x >> 4;
    const int mbase = blockIdx.x * BMg;
    const int nbase = blockIdx.y * BNg;

    double acc[8][4];
#pragma unroll
    for (int i = 0; i < 8; ++i)
#pragma unroll
        for (int j = 0; j < 4; ++j) acc[i][j] = 0.0;

    for (int kt = 0; kt < KTOT; kt += BKg) {
        /* A tile: 128 rows x 32 k (1024 float4, 4 per thread) -> transposed */
#pragma unroll
        for (int i = 0; i < 4; ++i) {
            int q  = threadIdx.x + 256 * i;
            int r  = q >> 3;
            int kq = (q & 7) << 2;
            float4 v = *(const float4*)(A + (size_t)(mbase + r) * KTOT + kt + kq);
            As[kq + 0][r] = v.x;
            As[kq + 1][r] = v.y;
            As[kq + 2][r] = v.z;
            As[kq + 3][r] = v.w;
        }
        /* B tile: 32 k x 128 n, direct */
#pragma unroll
        for (int i = 0; i < 4; ++i) {
            int q  = threadIdx.x + 256 * i;
            int kk = q >> 5;
            int nn = (q & 31) << 2;
            *(float4*)&Bs[kk][nn] =
                *(const float4*)(Bt + (size_t)(kt + kk) * NCOLS + nbase + nn);
        }
        __syncthreads();

#pragma unroll
        for (int k = 0; k < BKg; ++k) {
            double b2[4];
#pragma unroll
            for (int j = 0; j < 4; ++j)
                b2[j] = *(const double*)&Bs[k][tx * 8 + 2 * j];
            float4 a0 = *(const float4*)&As[k][ty * 8];
            float4 a1 = *(const float4*)&As[k][ty * 8 + 4];
            const float av[8] = {a0.x, a0.y, a0.z, a0.w, a1.x, a1.y, a1.z, a1.w};
#pragma unroll
            for (int i = 0; i < 8; ++i) {
                double a2 = pack2(av[i], av[i]);
#pragma unroll
                for (int j = 0; j < 4; ++j)
                    acc[i][j] = ffma2(a2, b2[j], acc[i][j]);
            }
        }
        __syncthreads();
    }

    /* store C + per-thread column sums */
    float csum[8], csq[8];
#pragma unroll
    for (int j = 0; j < 8; ++j) { csum[j] = 0.f; csq[j] = 0.f; }
#pragma unroll
    for (int i = 0; i < 8; ++i) {
        const int row = mbase + ty * 8 + i;
#pragma unroll
        for (int j = 0; j < 4; ++j) {
            float2 c = unpack2(acc[i][j]);
            *(float2*)(C + (size_t)row * NCOLS + nbase + tx * 8 + 2 * j) = c;
            csum[2 * j]     += c.x;
            csum[2 * j + 1] += c.y;
            csq[2 * j]      = fmaf(c.x, c.x, csq[2 * j]);
            csq[2 * j + 1]  = fmaf(c.y, c.y, csq[2 * j + 1]);
        }
    }
    /* block reduce over ty -> deterministic partials */
#pragma unroll
    for (int j = 0; j < 8; ++j) red[ty][tx * 8 + j] = csum[j];
    __syncthreads();
    if (ty == 0) {
#pragma unroll
        for (int j = 0; j < 8; ++j) {
            float s = 0.f;
#pragma unroll
            for (int t = 0; t < 16; ++t) s += red[t][tx * 8 + j];
            int c = statoff + nbase + tx * 8 + j;
            g_psum[(size_t)c * PMAX + blockIdx.x] = s;
        }
    }
    __syncthreads();
#pragma unroll
    for (int j = 0; j < 8; ++j) red[ty][tx * 8 + j] = csq[j];
    __syncthreads();
    if (ty == 0) {
#pragma unroll
        for (int j = 0; j < 8; ++j) {
            float s = 0.f;
#pragma unroll
            for (int t = 0; t < 16; ++t) s += red[t][tx * 8 + j];
            int c = statoff + nbase + tx * 8 + j;
            g_psq[(size_t)c * PMAX + blockIdx.x] = s;
        }
    }
}

/* ================= output: BN3 + ReLU + transpose ==================== */
/* y3 [P,256] -> out [B,256,N]; 32x32 smem tiles, block (32,8).          */
__global__ void out_kernel(const float* __restrict__ g3,
                           const float* __restrict__ b3,
                           float* __restrict__ out) {
    __shared__ float tile[32][33];
    const int b  = blockIdx.z;
    const int n0 = blockIdx.x * 32;
    const int o0 = blockIdx.y * 32;
    const int tx = threadIdx.x, ty = threadIdx.y;
    for (int i = ty; i < 32; i += 8) {
        int p = b * NN + n0 + i;
        tile[i][tx] = g_ybuf3[(size_t)p * 256 + o0 + tx];
    }
    __syncthreads();
    for (int i = ty; i < 32; i += 8) {
        const int o = o0 + i;
        const float mu = g_mu[192 + o], r = g_rs[192 + o];
        const float gg = g3[o], bb = b3[o];
        float y = tile[tx][i];
        out[((size_t)b * 256 + o) * NN + n0 + tx] =
            fmaxf(fmaf((y - mu) * r, gg, bb), 0.f);
    }
}

/* ================= launcher ========================================== */
extern "C" void kernel_launch(void* const* d_in, const int* in_sizes, int n_in,
                              void* d_out, int out_size) {
    const float* x  = (const float*)d_in[0];
    const float* W1 = (const float*)d_in[1];
    const float* g1 = (const float*)d_in[2];
    const float* b1 = (const float*)d_in[3];
    const float* W2 = (const float*)d_in[4];
    const float* g2 = (const float*)d_in[5];
    const float* b2 = (const float*)d_in[6];
    const float* W3 = (const float*)d_in[7];
    const float* g3 = (const float*)d_in[8];
    const float* b3 = (const float*)d_in[9];
    float* out = (float*)d_out;

    float* hbuf1; cudaGetSymbolAddress((void**)&hbuf1, g_hbuf1);
    float* ybuf2; cudaGetSymbolAddress((void**)&ybuf2, g_ybuf2);
    float* cat;   cudaGetSymbolAddress((void**)&cat,   g_cat);
    float* ybuf3; cudaGetSymbolAddress((void**)&ybuf3, g_ybuf3);
    float* w2t;   cudaGetSymbolAddress((void**)&w2t,   g_w2t);
    float* w3t;   cudaGetSymbolAddress((void**)&w3t,   g_w3t);

    /* prep: transpose W2, W3 */
    prep_kernel<<<192, 256>>>(W2, W3);

    /* kNN */
    knn_kernel<<<dim3(BB, NN / 256), 256>>>(x);

    /* y1 + BN1 partials */
    y1_kernel<<<M1 / 256, 256>>>(x, W1);
    finalize_kernel<<<64, 256>>>(0, M1 / 256, 1.0f / (float)M1);

    /* h1 + pool -> x1 */
    h1pool_kernel<<<NPTS / 4, 256>>>(g1, b1);

    /* GEMM2: y2 = h1 @ W2^T, BN2 partials */
    gemm_kernel<64, 128><<<dim3(M1 / BMg, 1), 256>>>(hbuf1, w2t, ybuf2, 64);
    finalize_kernel<<<128, 256>>>(64, M1 / BMg, 1.0f / (float)M1);

    /* h2 + pool -> x2 */
    h2pool_kernel<<<NPTS, 128>>>(g2, b2);

    /* GEMM3: y3 = cat @ W3^T, BN3 partials */
    gemm_kernel<192, 256><<<dim3(NPTS / BMg, 2), 256>>>(cat, w3t, ybuf3, 192);
    finalize_kernel<<<256, 256>>>(192, NPTS / BMg, 1.0f / (float)NPTS);

    /* output: BN3 + ReLU + transpose */
    out_kernel<<<dim3(NN / 32, 256 / 32, BB), dim3(32, 8)>>>(g3, b3, out);

    (void)in_sizes; (void)n_in; (void)out_size;
}